// round 14
// baseline (speedup 1.0000x reference)
#include <cuda_runtime.h>
#include <cuda_bf16.h>
#include <math.h>

#define B_  2
#define T_  2048
#define C_  1024
#define H_  16
#define D_  64
#define M_  (B_ * T_)     // 4096 rows
#define N3  (3 * C_)      // fused QKV width

// K-dim 16-group permutation (contraction dim only):
//   stored = [v0,v1,v8,v9, v2,v3,v10,v11, v4,v5,v12,v13, v6,v7,v14,v15]
// Thread qd's float4 at 16*kp+4*qd = {A[k8][2qd],A[k8][2qd+1],
// A[k8+1][2qd],A[k8+1][2qd+1]} -> one LDS.128 feeds TWO m16n8k8 steps.
// Slot map (slot qd = logical 2qd, slot qd+4 = logical 2qd+1) as before.

// ---------------- scratch (device globals: no allocation allowed) ----------
__device__ __align__(128) float g_qkv[(size_t)M_ * N3];    // fused q|k|v (plain)
__device__ __align__(128) float g_o[(size_t)M_ * C_];      // K-permuted cols
__device__ __align__(128) float g_xc[(size_t)M_ * C_];     // tf32 + K-perm
__device__ __align__(128) float g_wc[4][(size_t)C_ * C_];  // tf32 + K-perm
__device__ __align__(128) float2 g_rope_tab[T_ * 32];

// ---------------- helpers ----------------------------------------------------
__device__ __forceinline__ void cp16(void* smem_dst, const void* gmem_src) {
    unsigned s = (unsigned)__cvta_generic_to_shared(smem_dst);
    asm volatile("cp.async.cg.shared.global [%0], [%1], 16;\n"
                 :: "r"(s), "l"(gmem_src));
}
#define CP_COMMIT()  asm volatile("cp.async.commit_group;\n")
#define CP_WAIT(n)   asm volatile("cp.async.wait_group %0;\n" :: "n"(n))

__device__ __forceinline__ float tf32r(float f) {
    unsigned u;
    asm("cvt.rna.tf32.f32 %0, %1;" : "=r"(u) : "f"(f));
    return __uint_as_float(u);
}
__device__ __forceinline__ void mma8(float* d, const unsigned* a,
                                     const unsigned* b) {
    asm volatile(
        "mma.sync.aligned.m16n8k8.row.col.f32.tf32.tf32.f32 "
        "{%0,%1,%2,%3}, {%4,%5,%6,%7}, {%8,%9}, {%0,%1,%2,%3};"
        : "+f"(d[0]), "+f"(d[1]), "+f"(d[2]), "+f"(d[3])
        : "r"(a[0]), "r"(a[1]), "r"(a[2]), "r"(a[3]),
          "r"(b[0]), "r"(b[1]));
}

// ---------------------------------------------------------------------------
// prep: tf32-round + 16-group K-permute (in registers, fully vectorized)
// for x and ALL four weights, plus the RoPE table. ONE launch.
// ---------------------------------------------------------------------------
#define X16 (M_ * C_ / 16)
#define W16 (C_ * C_ / 16)
#define PREP_TOT (X16 + 4 * W16 + T_ * 32)

__global__ __launch_bounds__(256) void prep_kernel(
    const float* __restrict__ x,
    const float* __restrict__ Wq, const float* __restrict__ Wk,
    const float* __restrict__ Wv, const float* __restrict__ Wo,
    float* __restrict__ xc, float* __restrict__ wc,
    float2* __restrict__ tab)
{
    int i = blockIdx.x * blockDim.x + threadIdx.x;
    if (i >= PREP_TOT) return;
    if (i >= X16 + 4 * W16) {
        int idx = i - (X16 + 4 * W16);
        int t = idx >> 5;
        int j = idx & 31;
        double inv = exp(-((double)(2 * j) / 64.0) * log(10000.0));
        double ang = (double)t * inv;
        tab[idx] = make_float2((float)cos(ang), (float)sin(ang));
        return;
    }
    const float* src;
    float* dst;
    int idx;
    if (i < X16) {
        src = x; dst = xc; idx = i;
    } else {
        int r = i - X16;
        int which = r / W16;
        idx = r - which * W16;
        const float* ws[4] = {Wq, Wk, Wv, Wo};
        src = ws[which];
        dst = wc + (size_t)which * (C_ * C_);
    }
    float v[16];
#pragma unroll
    for (int q = 0; q < 4; q++) {
        float4 t4 = ((const float4*)src)[4 * idx + q];
        v[4 * q + 0] = tf32r(t4.x);
        v[4 * q + 1] = tf32r(t4.y);
        v[4 * q + 2] = tf32r(t4.z);
        v[4 * q + 3] = tf32r(t4.w);
    }
    ((float4*)dst)[4 * idx + 0] = make_float4(v[0], v[1], v[8],  v[9]);
    ((float4*)dst)[4 * idx + 1] = make_float4(v[2], v[3], v[10], v[11]);
    ((float4*)dst)[4 * idx + 2] = make_float4(v[4], v[5], v[12], v[13]);
    ((float4*)dst)[4 * idx + 3] = make_float4(v[6], v[7], v[14], v[15]);
}

// ---------------------------------------------------------------------------
// GEMM: Y[M,N] = A[M,K] @ B[N,K]^T, raw mma.sync m16n8k8 tf32.
// BOTH operands K-16-group-permuted -> LDS.128 fragment loads (one per TWO
// k8 steps). Swizzle: offset ^ ((row&1)<<4) -> phase-conflict-free stores
// and loads. 128x128 tile, 4 warps, BK=32, 3-stage, 1 barrier/iter, 2 CTA/SM.
// ROPE=true: rotate q/k (even,odd) col pairs in epilogue + tf32-round.
// ---------------------------------------------------------------------------
template <bool ROPE>
__global__ __launch_bounds__(128, 2) void gemm_tn(
    const float* __restrict__ A, const float* __restrict__ Bm,
    float* __restrict__ Y, const float2* __restrict__ tab,
    int M, int N, int K)
{
    extern __shared__ float sg[];
    float* As = sg;                    // 3 x 128 x 32
    float* Bs = sg + 3 * 4096;         // 3 x 128 x 32

    const int m0  = blockIdx.y * 128;
    const int n0  = blockIdx.x * 128;
    const int tid = threadIdx.x;
    const int w   = tid >> 5;
    const int wm  = w >> 1;
    const int wn  = w & 1;
    const int l   = tid & 31;
    const int g   = l >> 2;
    const int qd  = l & 3;
    const int sw  = (g & 1) << 4;      // row-parity XOR, bit 4

    float acc[4][8][4];
#pragma unroll
    for (int i = 0; i < 4; i++)
#pragma unroll
        for (int j = 0; j < 8; j++)
#pragma unroll
            for (int e = 0; e < 4; e++) acc[i][j][e] = 0.0f;

    auto load_stage = [&](int buf, int kc) {
#pragma unroll
        for (int i = tid; i < 1024; i += 128) {
            int r = i >> 3;
            int c = i & 7;
            int d = (4 * c) ^ ((r & 1) << 4);
            cp16(&As[buf * 4096 + r * 32 + d],
                 &A[(size_t)(m0 + r) * K + kc + 4 * c]);
            cp16(&Bs[buf * 4096 + r * 32 + d],
                 &Bm[(size_t)(n0 + r) * K + kc + 4 * c]);
        }
    };

    load_stage(0, 0);
    CP_COMMIT();
    load_stage(1, 32);
    CP_COMMIT();

    const int NIT = K / 32;
    for (int it = 0; it < NIT; it++) {
        if (it < NIT - 1) { CP_WAIT(1); } else { CP_WAIT(0); }
        __syncthreads();
        if (it + 2 < NIT) {
            load_stage((it + 2) % 3, (it + 2) * 32);
            CP_COMMIT();
        }

        const float* Ab = &As[(it % 3) * 4096 + (wm * 64) * 32];
        const float* Bb = &Bs[(it % 3) * 4096 + (wn * 64) * 32];

#pragma unroll
        for (int kp = 0; kp < 2; kp++) {
            const int ko = (16 * kp + 4 * qd) ^ sw;
            float4 alo[4], ahi[4];
#pragma unroll
            for (int i = 0; i < 4; i++) {
                alo[i] = *(const float4*)&Ab[(i * 16 + g)     * 32 + ko];
                ahi[i] = *(const float4*)&Ab[(i * 16 + g + 8) * 32 + ko];
            }
#pragma unroll
            for (int j = 0; j < 8; j++) {
                float4 b4 = *(const float4*)&Bb[(j * 8 + g) * 32 + ko];
                unsigned b0[2] = {__float_as_uint(b4.x), __float_as_uint(b4.y)};
                unsigned b1[2] = {__float_as_uint(b4.z), __float_as_uint(b4.w)};
#pragma unroll
                for (int i = 0; i < 4; i++) {
                    unsigned a0[4] = {__float_as_uint(alo[i].x),
                                      __float_as_uint(ahi[i].x),
                                      __float_as_uint(alo[i].y),
                                      __float_as_uint(ahi[i].y)};
                    unsigned a1[4] = {__float_as_uint(alo[i].z),
                                      __float_as_uint(ahi[i].z),
                                      __float_as_uint(alo[i].w),
                                      __float_as_uint(ahi[i].w)};
                    mma8(acc[i][j], a0, b0);
                    mma8(acc[i][j], a1, b1);
                }
            }
        }
    }

    // epilogue (RoPE fused for q/k columns when ROPE=true); N-dim plain
#pragma unroll
    for (int i = 0; i < 4; i++) {
        const int rA = m0 + wm * 64 + i * 16 + g;
        const int rB = rA + 8;
        const size_t rowA = (size_t)rA * N;
        const size_t rowB = (size_t)rB * N;
        const int tA = rA & (T_ - 1);
        const int tB = rB & (T_ - 1);
#pragma unroll
        for (int j = 0; j < 8; j++) {
            const int col = n0 + wn * 64 + j * 8 + 2 * qd;
            float e0 = acc[i][j][0], o0 = acc[i][j][1];
            float e1 = acc[i][j][2], o1 = acc[i][j][3];
            if (ROPE) {
                if (col < 2 * C_) {
                    const int jj = (col & (D_ - 1)) >> 1;
                    float2 csA = tab[tA * 32 + jj];
                    float2 csB = tab[tB * 32 + jj];
                    float ne0 = e0 * csA.x - o0 * csA.y;
                    float no0 = e0 * csA.y + o0 * csA.x;
                    float ne1 = e1 * csB.x - o1 * csB.y;
                    float no1 = e1 * csB.y + o1 * csB.x;
                    e0 = ne0; o0 = no0; e1 = ne1; o1 = no1;
                }
                e0 = tf32r(e0); o0 = tf32r(o0);
                e1 = tf32r(e1); o1 = tf32r(o1);
            }
            *(float2*)&Y[rowA + col] = make_float2(e0, o0);
            *(float2*)&Y[rowB + col] = make_float2(e1, o1);
        }
    }
}

// ---------------------------------------------------------------------------
// Flash attention (causal), FA-2 style (R13 structure, unchanged mainloop).
// Output ob written at K-PERMUTED column positions (still float2 stores,
// same store count) so the Wo GEMM reads a permuted A operand.
// ---------------------------------------------------------------------------
#define FST 72
#define VST 68

__global__ __launch_bounds__(128, 2) void flash_kernel(
    const float* __restrict__ qkv, float* __restrict__ o)
{
    extern __shared__ float sm[];
    float* Qs = sm;                     // 64*FST
    float* Kb = Qs + 64 * FST;          // 2 x 64*FST
    float* Vb = Kb + 128 * FST;         // 2 x 64*VST

    const int bh  = blockIdx.y;
    const int b   = bh >> 4;
    const int h   = bh & 15;
    const int q0  = (gridDim.x - 1 - blockIdx.x) * 64;
    const int tid = threadIdx.x;
    const int w   = tid >> 5;
    const int l   = tid & 31;
    const int g   = l >> 2;
    const int qd  = l & 3;
    const float scale = 0.125f;

    const size_t qbase = (size_t)(b * T_ + q0) * N3 + h * D_;
    const size_t orow  = (size_t)(b * T_ + q0) * C_ + h * D_;

    auto kv_load = [&](int buf, int n0) {
        const size_t kbase = (size_t)(b * T_ + n0) * N3 + h * D_ + C_;
#pragma unroll
        for (int i = tid; i < 1024; i += 128) {
            int r = i >> 4, c = (i & 15) << 2;
            cp16(&Kb[buf * 64 * FST + r * FST + c],
                 &qkv[kbase + (size_t)r * N3 + c]);
            cp16(&Vb[buf * 64 * VST + r * VST + c],
                 &qkv[kbase + (size_t)r * N3 + C_ + c]);
        }
    };

    kv_load(0, 0);
    CP_COMMIT();

    for (int i = tid; i < 1024; i += 128) {
        int r = i >> 4, c = (i & 15) << 2;
        float4 t4 = *(const float4*)&qkv[qbase + (size_t)r * N3 + c];
        t4.x *= scale; t4.y *= scale; t4.z *= scale; t4.w *= scale;
        *(float4*)&Qs[r * FST + c] = t4;
    }
    __syncthreads();

    unsigned aq[8][4];
    const float* Qw = Qs + w * 16 * FST;
#pragma unroll
    for (int kt = 0; kt < 8; kt++) {
        float2 va = *(const float2*)&Qw[g * FST + kt * 8 + 2 * qd];
        float2 vb = *(const float2*)&Qw[(g + 8) * FST + kt * 8 + 2 * qd];
        aq[kt][0] = __float_as_uint(va.x);
        aq[kt][1] = __float_as_uint(vb.x);
        aq[kt][2] = __float_as_uint(va.y);
        aq[kt][3] = __float_as_uint(vb.y);
    }

    float oacc[8][4];
#pragma unroll
    for (int nt = 0; nt < 8; nt++)
#pragma unroll
        for (int j = 0; j < 4; j++) oacc[nt][j] = 0.0f;
    float mA = -INFINITY, mB = -INFINITY, lA = 0.0f, lB = 0.0f;

    const int rA_loc = w * 16 + g;
    const int rB_loc = rA_loc + 8;

    for (int n0 = 0; n0 <= q0; n0 += 64) {
        const int buf = (n0 >> 6) & 1;
        CP_WAIT(0);
        __syncthreads();
        if (n0 + 64 <= q0) {
            kv_load(buf ^ 1, n0 + 64);
            CP_COMMIT();
        }

        const float* Ks = &Kb[buf * 64 * FST];
        const float* Vs = &Vb[buf * 64 * VST];

        float s[8][4];
#pragma unroll
        for (int nt = 0; nt < 8; nt++)
#pragma unroll
            for (int j = 0; j < 4; j++) s[nt][j] = 0.0f;

#pragma unroll
        for (int kt = 0; kt < 8; kt++) {
            unsigned bb[8][2];
#pragma unroll
            for (int nt = 0; nt < 8; nt++) {
                float2 kb = *(const float2*)&Ks[(nt * 8 + g) * FST + kt * 8 + 2 * qd];
                bb[nt][0] = __float_as_uint(kb.x);
                bb[nt][1] = __float_as_uint(kb.y);
            }
#pragma unroll
            for (int nt = 0; nt < 8; nt++)
                mma8(s[nt], aq[kt], bb[nt]);
        }

        if (n0 == q0) {
#pragma unroll
            for (int nt = 0; nt < 8; nt++) {
                int c0 = nt * 8 + 2 * qd;
                if (c0     > rA_loc) s[nt][0] = -INFINITY;
                if (c0 + 1 > rA_loc) s[nt][1] = -INFINITY;
                if (c0     > rB_loc) s[nt][2] = -INFINITY;
                if (c0 + 1 > rB_loc) s[nt][3] = -INFINITY;
            }
        }

        float mxA = -INFINITY, mxB = -INFINITY;
#pragma unroll
        for (int nt = 0; nt < 8; nt++) {
            mxA = fmaxf(mxA, fmaxf(s[nt][0], s[nt][1]));
            mxB = fmaxf(mxB, fmaxf(s[nt][2], s[nt][3]));
        }
        mxA = fmaxf(mxA, __shfl_xor_sync(0xffffffffu, mxA, 1));
        mxA = fmaxf(mxA, __shfl_xor_sync(0xffffffffu, mxA, 2));
        mxB = fmaxf(mxB, __shfl_xor_sync(0xffffffffu, mxB, 1));
        mxB = fmaxf(mxB, __shfl_xor_sync(0xffffffffu, mxB, 2));

        float nmA = fmaxf(mA, mxA);
        float nmB = fmaxf(mB, mxB);
        float alA = __expf(mA - nmA);
        float alB = __expf(mB - nmB);
        mA = nmA; mB = nmB;

        float sumA = 0.0f, sumB = 0.0f;
#pragma unroll
        for (int nt = 0; nt < 8; nt++) {
            float p0 = __expf(s[nt][0] - nmA);
            float p1 = __expf(s[nt][1] - nmA);
            float p2 = __expf(s[nt][2] - nmB);
            float p3 = __expf(s[nt][3] - nmB);
            s[nt][0] = p0; s[nt][1] = p1; s[nt][2] = p2; s[nt][3] = p3;
            sumA += p0 + p1;
            sumB += p2 + p3;
        }
        sumA += __shfl_xor_sync(0xffffffffu, sumA, 1);
        sumA += __shfl_xor_sync(0xffffffffu, sumA, 2);
        sumB += __shfl_xor_sync(0xffffffffu, sumB, 1);
        sumB += __shfl_xor_sync(0xffffffffu, sumB, 2);
        lA = lA * alA + sumA;
        lB = lB * alB + sumB;

#pragma unroll
        for (int nt = 0; nt < 8; nt++) {
            oacc[nt][0] *= alA; oacc[nt][1] *= alA;
            oacc[nt][2] *= alB; oacc[nt][3] *= alB;
        }

        // O += P V : P straight from S accumulators (slot-remap identity)
#pragma unroll
        for (int kt = 0; kt < 8; kt++) {
            unsigned ap[4];
            ap[0] = __float_as_uint(tf32r(s[kt][0]));
            ap[1] = __float_as_uint(tf32r(s[kt][2]));
            ap[2] = __float_as_uint(tf32r(s[kt][1]));
            ap[3] = __float_as_uint(tf32r(s[kt][3]));
            unsigned vv[8][2];
#pragma unroll
            for (int nt = 0; nt < 8; nt++) {
                vv[nt][0] = __float_as_uint(Vs[(kt * 8 + 2 * qd)     * VST + nt * 8 + g]);
                vv[nt][1] = __float_as_uint(Vs[(kt * 8 + 2 * qd + 1) * VST + nt * 8 + g]);
            }
#pragma unroll
            for (int nt = 0; nt < 8; nt++)
                mma8(oacc[nt], ap, vv[nt]);
        }
    }

    // normalize + write at K-PERMUTED column positions (float2, same count):
    // logical col 8*nt+2*qd -> pos 16*(nt>>1) + 4*qd + 2*(nt&1)
    const float rAi = 1.0f / lA;
    const float rBi = 1.0f / lB;
#pragma unroll
    for (int nt = 0; nt < 8; nt++) {
        int cp = ((nt >> 1) << 4) + 4 * qd + ((nt & 1) << 1);
        *(float2*)&o[orow + (size_t)rA_loc * C_ + cp] =
            make_float2(tf32r(oacc[nt][0] * rAi), tf32r(oacc[nt][1] * rAi));
        *(float2*)&o[orow + (size_t)rB_loc * C_ + cp] =
            make_float2(tf32r(oacc[nt][2] * rBi), tf32r(oacc[nt][3] * rBi));
    }
}

// ---------------------------------------------------------------------------
extern "C" void kernel_launch(void* const* d_in, const int* in_sizes, int n_in,
                              void* d_out, int out_size)
{
    (void)in_sizes; (void)n_in; (void)out_size;
    const float* x  = (const float*)d_in[0];
    const float* Wq = (const float*)d_in[1];
    const float* Wk = (const float*)d_in[2];
    const float* Wv = (const float*)d_in[3];
    const float* Wo = (const float*)d_in[4];
    float* out = (float*)d_out;

    float *qkv, *ob, *xc, *wc;
    float2* tab;
    cudaGetSymbolAddress((void**)&qkv, g_qkv);
    cudaGetSymbolAddress((void**)&ob,  g_o);
    cudaGetSymbolAddress((void**)&xc,  g_xc);
    cudaGetSymbolAddress((void**)&wc,  g_wc);
    cudaGetSymbolAddress((void**)&tab, g_rope_tab);

    float* wqkv = wc;                          // [3C][C], K-permuted
    float* woc  = wc + 3 * (size_t)C_ * C_;    // K-permuted

    prep_kernel<<<(PREP_TOT + 255) / 256, 256>>>(x, Wq, Wk, Wv, Wo,
                                                 xc, wc, tab);

    const int gsmem = 6 * 4096 * (int)sizeof(float);        // 98,304 B
    cudaFuncSetAttribute(gemm_tn<true>,
                         cudaFuncAttributeMaxDynamicSharedMemorySize, gsmem);
    cudaFuncSetAttribute(gemm_tn<false>,
                         cudaFuncAttributeMaxDynamicSharedMemorySize, gsmem);

    // fused QKV projection + RoPE epilogue (permuted inputs, plain output)
    gemm_tn<true><<<dim3(N3 / 128, M_ / 128), 128, gsmem>>>(
        xc, wqkv, qkv, tab, M_, N3, C_);

    const int fsmem = (64 * FST + 128 * FST + 128 * VST) * (int)sizeof(float);
    cudaFuncSetAttribute(flash_kernel,
                         cudaFuncAttributeMaxDynamicSharedMemorySize, fsmem);
    flash_kernel<<<dim3(T_ / 64, B_ * H_), 128, fsmem>>>(qkv, ob);

    // Wo GEMM: ob (permuted by flash) @ woc (permuted by prep)
    gemm_tn<false><<<dim3(C_ / 128, M_ / 128), 128, gsmem>>>(
        ob, woc, out, tab, M_, C_, C_);
}

// round 15
// speedup vs baseline: 1.0813x; 1.0813x over previous
#include <cuda_runtime.h>
#include <cuda_bf16.h>
#include <math.h>

#define B_  2
#define T_  2048
#define C_  1024
#define H_  16
#define D_  64
#define M_  (B_ * T_)     // 4096 rows
#define N3  (3 * C_)      // fused QKV width

// mma k-slot remap: slots (qd, qd+4) hold LOGICAL elements (2qd, 2qd+1).
// Fragment pairs memory-adjacent -> LDS.64 with unpermuted data; in flash the
// S accumulators directly ARE the PV A-fragment. V is produced TRANSPOSED
// ([b][d][T]) by the QKV GEMM epilogue so PV B-fragments are float2 loads.

// ---------------- scratch (device globals: no allocation allowed) ----------
__device__ __align__(128) float g_qkv[(size_t)M_ * N3];    // q|k (v third unused)
__device__ __align__(128) float g_vT[(size_t)M_ * C_];     // V transposed
__device__ __align__(128) float g_o[(size_t)M_ * C_];
__device__ __align__(128) float g_xc[(size_t)M_ * C_];     // tf32-rounded x
__device__ __align__(128) float g_wc[4][(size_t)C_ * C_];  // tf32 Wq|Wk|Wv|Wo
__device__ __align__(128) float2 g_rope_tab[T_ * 32];

// ---------------- helpers ----------------------------------------------------
__device__ __forceinline__ void cp16(void* smem_dst, const void* gmem_src) {
    unsigned s = (unsigned)__cvta_generic_to_shared(smem_dst);
    asm volatile("cp.async.cg.shared.global [%0], [%1], 16;\n"
                 :: "r"(s), "l"(gmem_src));
}
#define CP_COMMIT()  asm volatile("cp.async.commit_group;\n")
#define CP_WAIT(n)   asm volatile("cp.async.wait_group %0;\n" :: "n"(n))

__device__ __forceinline__ float tf32r(float f) {
    unsigned u;
    asm("cvt.rna.tf32.f32 %0, %1;" : "=r"(u) : "f"(f));
    return __uint_as_float(u);
}
__device__ __forceinline__ void mma8(float* d, const unsigned* a,
                                     const unsigned* b) {
    asm volatile(
        "mma.sync.aligned.m16n8k8.row.col.f32.tf32.tf32.f32 "
        "{%0,%1,%2,%3}, {%4,%5,%6,%7}, {%8,%9}, {%0,%1,%2,%3};"
        : "+f"(d[0]), "+f"(d[1]), "+f"(d[2]), "+f"(d[3])
        : "r"(a[0]), "r"(a[1]), "r"(a[2]), "r"(a[3]),
          "r"(b[0]), "r"(b[1]));
}

// ---------------------------------------------------------------------------
// prep: tf32 rounding for x + 4 weights + RoPE table, ONE launch (R13 form)
// ---------------------------------------------------------------------------
#define XN4 (M_ * C_ / 4)
#define WN4 (C_ * C_ / 4)
#define PREP_TOT (XN4 + 4 * WN4 + T_ * 32)

__global__ __launch_bounds__(256) void prep_kernel(
    const float* __restrict__ x,
    const float* __restrict__ Wq, const float* __restrict__ Wk,
    const float* __restrict__ Wv, const float* __restrict__ Wo,
    float* __restrict__ xc, float* __restrict__ wc,
    float2* __restrict__ tab)
{
    int i = blockIdx.x * blockDim.x + threadIdx.x;
    if (i >= PREP_TOT) return;
    if (i >= XN4 + 4 * WN4) {
        int idx = i - (XN4 + 4 * WN4);
        int t = idx >> 5;
        int j = idx & 31;
        double inv = exp(-((double)(2 * j) / 64.0) * log(10000.0));
        double ang = (double)t * inv;
        tab[idx] = make_float2((float)cos(ang), (float)sin(ang));
        return;
    }
    const float* src;
    float* dst;
    int idx;
    if (i < XN4) {
        src = x; dst = xc; idx = i;
    } else {
        int r = i - XN4;
        int which = r / WN4;
        idx = r - which * WN4;
        const float* ws[4] = {Wq, Wk, Wv, Wo};
        src = ws[which];
        dst = wc + (size_t)which * (C_ * C_);
    }
    float4 t = ((const float4*)src)[idx];
    t.x = tf32r(t.x); t.y = tf32r(t.y); t.z = tf32r(t.z); t.w = tf32r(t.w);
    ((float4*)dst)[idx] = t;
}

// ---------------------------------------------------------------------------
// GEMM (R13 form): raw mma.sync m16n8k8 tf32, slot-remapped LDS.64 fragment
// loads, ST=32 + XOR swizzle ((row&3)<<3), 128x128 tile, 4 warps, BK=32,
// 3-stage cp.async, one barrier/iter, 2 CTAs/SM.
// ROPE=true epilogue: q/k cols -> RoPE + tf32r -> Y; v cols -> tf32r ->
// TRANSPOSED store into vT[b][d][T] (per-CTA-uniform branch).
// ---------------------------------------------------------------------------
template <bool ROPE>
__global__ __launch_bounds__(128, 2) void gemm_tn(
    const float* __restrict__ A, const float* __restrict__ Bm,
    float* __restrict__ Y, float* __restrict__ vT,
    const float2* __restrict__ tab, int M, int N, int K)
{
    extern __shared__ float sg[];
    float* As = sg;                    // 3 x 128 x 32
    float* Bs = sg + 3 * 4096;         // 3 x 128 x 32

    const int m0  = blockIdx.y * 128;
    const int n0  = blockIdx.x * 128;
    const int tid = threadIdx.x;
    const int w   = tid >> 5;
    const int wm  = w >> 1;
    const int wn  = w & 1;
    const int l   = tid & 31;
    const int g   = l >> 2;
    const int qd  = l & 3;
    const int swz = (g & 3) << 3;

    float acc[4][8][4];
#pragma unroll
    for (int i = 0; i < 4; i++)
#pragma unroll
        for (int j = 0; j < 8; j++)
#pragma unroll
            for (int e = 0; e < 4; e++) acc[i][j][e] = 0.0f;

    auto load_stage = [&](int buf, int kc) {
#pragma unroll
        for (int i = tid; i < 1024; i += 128) {
            int r = i >> 3;
            int c = i & 7;
            int d = (4 * c) ^ ((r & 3) << 3);
            cp16(&As[buf * 4096 + r * 32 + d],
                 &A[(size_t)(m0 + r) * K + kc + 4 * c]);
            cp16(&Bs[buf * 4096 + r * 32 + d],
                 &Bm[(size_t)(n0 + r) * K + kc + 4 * c]);
        }
    };

    load_stage(0, 0);
    CP_COMMIT();
    load_stage(1, 32);
    CP_COMMIT();

    const int NIT = K / 32;
    for (int it = 0; it < NIT; it++) {
        if (it < NIT - 1) { CP_WAIT(1); } else { CP_WAIT(0); }
        __syncthreads();
        if (it + 2 < NIT) {
            load_stage((it + 2) % 3, (it + 2) * 32);
            CP_COMMIT();
        }

        const float* Ab = &As[(it % 3) * 4096 + (wm * 64) * 32];
        const float* Bb = &Bs[(it % 3) * 4096 + (wn * 64) * 32];

#pragma unroll
        for (int k8 = 0; k8 < 4; k8++) {
            const int ko = (8 * k8 + 2 * qd) ^ swz;
            unsigned av[4][4];
#pragma unroll
            for (int i = 0; i < 4; i++) {
                float2 va = *(const float2*)&Ab[(i * 16 + g)     * 32 + ko];
                float2 vc = *(const float2*)&Ab[(i * 16 + g + 8) * 32 + ko];
                av[i][0] = __float_as_uint(va.x);
                av[i][1] = __float_as_uint(vc.x);
                av[i][2] = __float_as_uint(va.y);
                av[i][3] = __float_as_uint(vc.y);
            }
            unsigned bv[8][2];
#pragma unroll
            for (int j = 0; j < 8; j++) {
                float2 vb = *(const float2*)&Bb[(j * 8 + g) * 32 + ko];
                bv[j][0] = __float_as_uint(vb.x);
                bv[j][1] = __float_as_uint(vb.y);
            }
#pragma unroll
            for (int i = 0; i < 4; i++)
#pragma unroll
                for (int j = 0; j < 8; j++)
                    mma8(acc[i][j], av[i], bv[j]);
        }
    }

    // epilogue
    const bool vpart = ROPE && (n0 >= 2 * C_);   // uniform per CTA
#pragma unroll
    for (int i = 0; i < 4; i++) {
        const int rA = m0 + wm * 64 + i * 16 + g;
        const int rB = rA + 8;
        const size_t rowA = (size_t)rA * N;
        const size_t rowB = (size_t)rB * N;
        const int tA = rA & (T_ - 1);
        const int tB = rB & (T_ - 1);
        const int bA = rA >> 11;                 // T_ = 2048
#pragma unroll
        for (int j = 0; j < 8; j++) {
            const int col = n0 + wn * 64 + j * 8 + 2 * qd;
            float e0 = acc[i][j][0], o0 = acc[i][j][1];
            float e1 = acc[i][j][2], o1 = acc[i][j][3];
            if (ROPE) {
                if (!vpart) {
                    // q or k column pair: rotate
                    const int jj = (col & (D_ - 1)) >> 1;
                    float2 csA = tab[tA * 32 + jj];
                    float2 csB = tab[tB * 32 + jj];
                    float ne0 = e0 * csA.x - o0 * csA.y;
                    float no0 = e0 * csA.y + o0 * csA.x;
                    float ne1 = e1 * csB.x - o1 * csB.y;
                    float no1 = e1 * csB.y + o1 * csB.x;
                    *(float2*)&Y[rowA + col] =
                        make_float2(tf32r(ne0), tf32r(no0));
                    *(float2*)&Y[rowB + col] =
                        make_float2(tf32r(ne1), tf32r(no1));
                } else {
                    // v column pair: transposed store into vT[b][d][T]
                    const int dv = col - 2 * C_;
                    float* vb = vT + ((size_t)bA * C_ + dv) * T_;
                    vb[tA]      = tf32r(e0);
                    vb[T_ + tA] = tf32r(o0);
                    vb[tB]      = tf32r(e1);
                    vb[T_ + tB] = tf32r(o1);
                }
            } else {
                *(float2*)&Y[rowA + col] = make_float2(e0, o0);
                *(float2*)&Y[rowB + col] = make_float2(e1, o1);
            }
        }
    }
}

// ---------------------------------------------------------------------------
// Flash attention (causal), FA-2 style, slot-remapped fragments.
// P straight from S accumulators (no smem round-trip). V is read from the
// TRANSPOSED vT buffer -> PV B-fragments are float2 LDS.64 (was 128 LDS.32).
// FST=72 (Q/K), VST=72 (V^T) - both phase-conflict-free. 2 CTAs/SM.
// ---------------------------------------------------------------------------
#define FST 72
#define VST 72

__global__ __launch_bounds__(128, 2) void flash_kernel(
    const float* __restrict__ qkv, const float* __restrict__ vT,
    float* __restrict__ o)
{
    extern __shared__ float sm[];
    float* Qs = sm;                     // 64*FST
    float* Kb = Qs + 64 * FST;          // 2 x 64*FST
    float* Vb = Kb + 128 * FST;         // 2 x 64*VST  (V^T tiles: [d][n])

    const int bh  = blockIdx.y;
    const int b   = bh >> 4;
    const int h   = bh & 15;
    const int q0  = (gridDim.x - 1 - blockIdx.x) * 64;
    const int tid = threadIdx.x;
    const int w   = tid >> 5;
    const int l   = tid & 31;
    const int g   = l >> 2;
    const int qd  = l & 3;
    const float scale = 0.125f;

    const size_t qbase = (size_t)(b * T_ + q0) * N3 + h * D_;
    const size_t vbase = ((size_t)b * C_ + h * D_) * T_;   // vT row base
    const size_t orow  = (size_t)(b * T_ + q0) * C_ + h * D_;

    auto kv_load = [&](int buf, int n0) {
        const size_t kbase = (size_t)(b * T_ + n0) * N3 + h * D_ + C_;
#pragma unroll
        for (int i = tid; i < 1024; i += 128) {
            int r = i >> 4, c = (i & 15) << 2;
            cp16(&Kb[buf * 64 * FST + r * FST + c],
                 &qkv[kbase + (size_t)r * N3 + c]);
            cp16(&Vb[buf * 64 * VST + r * VST + c],
                 &vT[vbase + (size_t)r * T_ + n0 + c]);
        }
    };

    kv_load(0, 0);
    CP_COMMIT();

    for (int i = tid; i < 1024; i += 128) {
        int r = i >> 4, c = (i & 15) << 2;
        float4 t4 = *(const float4*)&qkv[qbase + (size_t)r * N3 + c];
        t4.x *= scale; t4.y *= scale; t4.z *= scale; t4.w *= scale;
        *(float4*)&Qs[r * FST + c] = t4;
    }
    __syncthreads();

    unsigned aq[8][4];
    const float* Qw = Qs + w * 16 * FST;
#pragma unroll
    for (int kt = 0; kt < 8; kt++) {
        float2 va = *(const float2*)&Qw[g * FST + kt * 8 + 2 * qd];
        float2 vb = *(const float2*)&Qw[(g + 8) * FST + kt * 8 + 2 * qd];
        aq[kt][0] = __float_as_uint(va.x);
        aq[kt][1] = __float_as_uint(vb.x);
        aq[kt][2] = __float_as_uint(va.y);
        aq[kt][3] = __float_as_uint(vb.y);
    }

    float oacc[8][4];
#pragma unroll
    for (int nt = 0; nt < 8; nt++)
#pragma unroll
        for (int j = 0; j < 4; j++) oacc[nt][j] = 0.0f;
    float mA = -INFINITY, mB = -INFINITY, lA = 0.0f, lB = 0.0f;

    const int rA_loc = w * 16 + g;
    const int rB_loc = rA_loc + 8;

    for (int n0 = 0; n0 <= q0; n0 += 64) {
        const int buf = (n0 >> 6) & 1;
        CP_WAIT(0);
        __syncthreads();
        if (n0 + 64 <= q0) {
            kv_load(buf ^ 1, n0 + 64);
            CP_COMMIT();
        }

        const float* Ks = &Kb[buf * 64 * FST];
        const float* Vs = &Vb[buf * 64 * VST];

        float s[8][4];
#pragma unroll
        for (int nt = 0; nt < 8; nt++)
#pragma unroll
            for (int j = 0; j < 4; j++) s[nt][j] = 0.0f;

#pragma unroll
        for (int kt = 0; kt < 8; kt++) {
            unsigned bb[8][2];
#pragma unroll
            for (int nt = 0; nt < 8; nt++) {
                float2 kb = *(const float2*)&Ks[(nt * 8 + g) * FST + kt * 8 + 2 * qd];
                bb[nt][0] = __float_as_uint(kb.x);
                bb[nt][1] = __float_as_uint(kb.y);
            }
#pragma unroll
            for (int nt = 0; nt < 8; nt++)
                mma8(s[nt], aq[kt], bb[nt]);
        }

        if (n0 == q0) {
#pragma unroll
            for (int nt = 0; nt < 8; nt++) {
                int c0 = nt * 8 + 2 * qd;
                if (c0     > rA_loc) s[nt][0] = -INFINITY;
                if (c0 + 1 > rA_loc) s[nt][1] = -INFINITY;
                if (c0     > rB_loc) s[nt][2] = -INFINITY;
                if (c0 + 1 > rB_loc) s[nt][3] = -INFINITY;
            }
        }

        float mxA = -INFINITY, mxB = -INFINITY;
#pragma unroll
        for (int nt = 0; nt < 8; nt++) {
            mxA = fmaxf(mxA, fmaxf(s[nt][0], s[nt][1]));
            mxB = fmaxf(mxB, fmaxf(s[nt][2], s[nt][3]));
        }
        mxA = fmaxf(mxA, __shfl_xor_sync(0xffffffffu, mxA, 1));
        mxA = fmaxf(mxA, __shfl_xor_sync(0xffffffffu, mxA, 2));
        mxB = fmaxf(mxB, __shfl_xor_sync(0xffffffffu, mxB, 1));
        mxB = fmaxf(mxB, __shfl_xor_sync(0xffffffffu, mxB, 2));

        float nmA = fmaxf(mA, mxA);
        float nmB = fmaxf(mB, mxB);
        float alA = __expf(mA - nmA);
        float alB = __expf(mB - nmB);
        mA = nmA; mB = nmB;

        float sumA = 0.0f, sumB = 0.0f;
#pragma unroll
        for (int nt = 0; nt < 8; nt++) {
            float p0 = __expf(s[nt][0] - nmA);
            float p1 = __expf(s[nt][1] - nmA);
            float p2 = __expf(s[nt][2] - nmB);
            float p3 = __expf(s[nt][3] - nmB);
            s[nt][0] = p0; s[nt][1] = p1; s[nt][2] = p2; s[nt][3] = p3;
            sumA += p0 + p1;
            sumB += p2 + p3;
        }
        sumA += __shfl_xor_sync(0xffffffffu, sumA, 1);
        sumA += __shfl_xor_sync(0xffffffffu, sumA, 2);
        sumB += __shfl_xor_sync(0xffffffffu, sumB, 1);
        sumB += __shfl_xor_sync(0xffffffffu, sumB, 2);
        lA = lA * alA + sumA;
        lB = lB * alB + sumB;

#pragma unroll
        for (int nt = 0; nt < 8; nt++) {
            oacc[nt][0] *= alA; oacc[nt][1] *= alA;
            oacc[nt][2] *= alB; oacc[nt][3] *= alB;
        }

        // O += P V : P straight from S accumulators; V^T gives float2 B-frags
#pragma unroll
        for (int kt = 0; kt < 8; kt++) {
            unsigned ap[4];
            ap[0] = __float_as_uint(tf32r(s[kt][0]));
            ap[1] = __float_as_uint(tf32r(s[kt][2]));
            ap[2] = __float_as_uint(tf32r(s[kt][1]));
            ap[3] = __float_as_uint(tf32r(s[kt][3]));
            unsigned vv[8][2];
#pragma unroll
            for (int nt = 0; nt < 8; nt++) {
                float2 v2 = *(const float2*)&Vs[(nt * 8 + g) * VST + kt * 8 + 2 * qd];
                vv[nt][0] = __float_as_uint(v2.x);
                vv[nt][1] = __float_as_uint(v2.y);
            }
#pragma unroll
            for (int nt = 0; nt < 8; nt++)
                mma8(oacc[nt], ap, vv[nt]);
        }
    }

    const float rAi = 1.0f / lA;
    const float rBi = 1.0f / lB;
#pragma unroll
    for (int nt = 0; nt < 8; nt++) {
        int c0 = nt * 8 + 2 * qd;
        *(float2*)&o[orow + (size_t)rA_loc * C_ + c0] =
            make_float2(tf32r(oacc[nt][0] * rAi), tf32r(oacc[nt][1] * rAi));
        *(float2*)&o[orow + (size_t)rB_loc * C_ + c0] =
            make_float2(tf32r(oacc[nt][2] * rBi), tf32r(oacc[nt][3] * rBi));
    }
}

// ---------------------------------------------------------------------------
extern "C" void kernel_launch(void* const* d_in, const int* in_sizes, int n_in,
                              void* d_out, int out_size)
{
    (void)in_sizes; (void)n_in; (void)out_size;
    const float* x  = (const float*)d_in[0];
    const float* Wq = (const float*)d_in[1];
    const float* Wk = (const float*)d_in[2];
    const float* Wv = (const float*)d_in[3];
    const float* Wo = (const float*)d_in[4];
    float* out = (float*)d_out;

    float *qkv, *vT, *ob, *xc, *wc;
    float2* tab;
    cudaGetSymbolAddress((void**)&qkv, g_qkv);
    cudaGetSymbolAddress((void**)&vT,  g_vT);
    cudaGetSymbolAddress((void**)&ob,  g_o);
    cudaGetSymbolAddress((void**)&xc,  g_xc);
    cudaGetSymbolAddress((void**)&wc,  g_wc);
    cudaGetSymbolAddress((void**)&tab, g_rope_tab);

    float* wqkv = wc;                          // [3C][C], contiguous
    float* woc  = wc + 3 * (size_t)C_ * C_;

    prep_kernel<<<(PREP_TOT + 255) / 256, 256>>>(x, Wq, Wk, Wv, Wo,
                                                 xc, wc, tab);

    const int gsmem = 6 * 4096 * (int)sizeof(float);        // 98,304 B
    cudaFuncSetAttribute(gemm_tn<true>,
                         cudaFuncAttributeMaxDynamicSharedMemorySize, gsmem);
    cudaFuncSetAttribute(gemm_tn<false>,
                         cudaFuncAttributeMaxDynamicSharedMemorySize, gsmem);

    // fused QKV projection + RoPE epilogue; v third written transposed to vT
    gemm_tn<true><<<dim3(N3 / 128, M_ / 128), 128, gsmem>>>(
        xc, wqkv, qkv, vT, tab, M_, N3, C_);

    const int fsmem = (64 * FST + 128 * FST + 128 * VST) * (int)sizeof(float);
    cudaFuncSetAttribute(flash_kernel,
                         cudaFuncAttributeMaxDynamicSharedMemorySize, fsmem);
    flash_kernel<<<dim3(T_ / 64, B_ * H_), 128, fsmem>>>(qkv, vT, ob);

    gemm_tn<false><<<dim3(C_ / 128, M_ / 128), 128, gsmem>>>(
        ob, woc, out, nullptr, tab, M_, C_, C_);
}

// round 16
// speedup vs baseline: 1.1194x; 1.0353x over previous
#include <cuda_runtime.h>
#include <cuda_bf16.h>
#include <math.h>

#define B_  2
#define T_  2048
#define C_  1024
#define H_  16
#define D_  64
#define M_  (B_ * T_)     // 4096 rows
#define N3  (3 * C_)      // fused QKV width

// mma k-slot remap: slots (qd, qd+4) hold LOGICAL elements (2qd, 2qd+1).
// Fragment pairs memory-adjacent -> LDS.64; S accumulators directly ARE the
// PV A-fragment; V produced TRANSPOSED ([b][d][T]) by the QKV GEMM epilogue.

// ---------------- scratch (device globals: no allocation allowed) ----------
__device__ __align__(128) float g_qkv[(size_t)M_ * N3];    // q|k (v third unused)
__device__ __align__(128) float g_vT[(size_t)M_ * C_];     // V transposed
__device__ __align__(128) float g_o[(size_t)M_ * C_];
__device__ __align__(128) float g_xc[(size_t)M_ * C_];     // tf32-rounded x
__device__ __align__(128) float g_wc[4][(size_t)C_ * C_];  // tf32 Wq|Wk|Wv|Wo
__device__ __align__(128) float2 g_rope_tab[T_ * 32];

// ---------------- helpers ----------------------------------------------------
__device__ __forceinline__ void cp16(void* smem_dst, const void* gmem_src) {
    unsigned s = (unsigned)__cvta_generic_to_shared(smem_dst);
    asm volatile("cp.async.cg.shared.global [%0], [%1], 16;\n"
                 :: "r"(s), "l"(gmem_src));
}
#define CP_COMMIT()  asm volatile("cp.async.commit_group;\n")
#define CP_WAIT(n)   asm volatile("cp.async.wait_group %0;\n" :: "n"(n))

__device__ __forceinline__ float tf32r(float f) {
    unsigned u;
    asm("cvt.rna.tf32.f32 %0, %1;" : "=r"(u) : "f"(f));
    return __uint_as_float(u);
}
__device__ __forceinline__ float ex2f(float x) {
    float y;
    asm("ex2.approx.f32 %0, %1;" : "=f"(y) : "f"(x));
    return y;
}
__device__ __forceinline__ void mma8(float* d, const unsigned* a,
                                     const unsigned* b) {
    asm volatile(
        "mma.sync.aligned.m16n8k8.row.col.f32.tf32.tf32.f32 "
        "{%0,%1,%2,%3}, {%4,%5,%6,%7}, {%8,%9}, {%0,%1,%2,%3};"
        : "+f"(d[0]), "+f"(d[1]), "+f"(d[2]), "+f"(d[3])
        : "r"(a[0]), "r"(a[1]), "r"(a[2]), "r"(a[3]),
          "r"(b[0]), "r"(b[1]));
}

// ---------------------------------------------------------------------------
// prep: tf32 rounding for x + 4 weights + RoPE table, ONE launch
// ---------------------------------------------------------------------------
#define XN4 (M_ * C_ / 4)
#define WN4 (C_ * C_ / 4)
#define PREP_TOT (XN4 + 4 * WN4 + T_ * 32)

__global__ __launch_bounds__(256) void prep_kernel(
    const float* __restrict__ x,
    const float* __restrict__ Wq, const float* __restrict__ Wk,
    const float* __restrict__ Wv, const float* __restrict__ Wo,
    float* __restrict__ xc, float* __restrict__ wc,
    float2* __restrict__ tab)
{
    int i = blockIdx.x * blockDim.x + threadIdx.x;
    if (i >= PREP_TOT) return;
    if (i >= XN4 + 4 * WN4) {
        int idx = i - (XN4 + 4 * WN4);
        int t = idx >> 5;
        int j = idx & 31;
        double inv = exp(-((double)(2 * j) / 64.0) * log(10000.0));
        double ang = (double)t * inv;
        tab[idx] = make_float2((float)cos(ang), (float)sin(ang));
        return;
    }
    const float* src;
    float* dst;
    int idx;
    if (i < XN4) {
        src = x; dst = xc; idx = i;
    } else {
        int r = i - XN4;
        int which = r / WN4;
        idx = r - which * WN4;
        const float* ws[4] = {Wq, Wk, Wv, Wo};
        src = ws[which];
        dst = wc + (size_t)which * (C_ * C_);
    }
    float4 t = ((const float4*)src)[idx];
    t.x = tf32r(t.x); t.y = tf32r(t.y); t.z = tf32r(t.z); t.w = tf32r(t.w);
    ((float4*)dst)[idx] = t;
}

// ---------------------------------------------------------------------------
// GEMM (R13/R15 form): raw mma.sync m16n8k8 tf32, slot-remapped LDS.64,
// ST=32 + XOR swizzle ((row&3)<<3), 128x128 tile, 4 warps, BK=32, 3-stage,
// one barrier/iter, 2 CTAs/SM.
// ROPE=true epilogue: q/k -> RoPE+tf32r -> Y; v -> tf32r -> vT[b][d][T].
// ---------------------------------------------------------------------------
template <bool ROPE>
__global__ __launch_bounds__(128, 2) void gemm_tn(
    const float* __restrict__ A, const float* __restrict__ Bm,
    float* __restrict__ Y, float* __restrict__ vT,
    const float2* __restrict__ tab, int M, int N, int K)
{
    extern __shared__ float sg[];
    float* As = sg;                    // 3 x 128 x 32
    float* Bs = sg + 3 * 4096;         // 3 x 128 x 32

    const int m0  = blockIdx.y * 128;
    const int n0  = blockIdx.x * 128;
    const int tid = threadIdx.x;
    const int w   = tid >> 5;
    const int wm  = w >> 1;
    const int wn  = w & 1;
    const int l   = tid & 31;
    const int g   = l >> 2;
    const int qd  = l & 3;
    const int swz = (g & 3) << 3;

    float acc[4][8][4];
#pragma unroll
    for (int i = 0; i < 4; i++)
#pragma unroll
        for (int j = 0; j < 8; j++)
#pragma unroll
            for (int e = 0; e < 4; e++) acc[i][j][e] = 0.0f;

    auto load_stage = [&](int buf, int kc) {
#pragma unroll
        for (int i = tid; i < 1024; i += 128) {
            int r = i >> 3;
            int c = i & 7;
            int d = (4 * c) ^ ((r & 3) << 3);
            cp16(&As[buf * 4096 + r * 32 + d],
                 &A[(size_t)(m0 + r) * K + kc + 4 * c]);
            cp16(&Bs[buf * 4096 + r * 32 + d],
                 &Bm[(size_t)(n0 + r) * K + kc + 4 * c]);
        }
    };

    load_stage(0, 0);
    CP_COMMIT();
    load_stage(1, 32);
    CP_COMMIT();

    const int NIT = K / 32;
    for (int it = 0; it < NIT; it++) {
        if (it < NIT - 1) { CP_WAIT(1); } else { CP_WAIT(0); }
        __syncthreads();
        if (it + 2 < NIT) {
            load_stage((it + 2) % 3, (it + 2) * 32);
            CP_COMMIT();
        }

        const float* Ab = &As[(it % 3) * 4096 + (wm * 64) * 32];
        const float* Bb = &Bs[(it % 3) * 4096 + (wn * 64) * 32];

#pragma unroll
        for (int k8 = 0; k8 < 4; k8++) {
            const int ko = (8 * k8 + 2 * qd) ^ swz;
            unsigned av[4][4];
#pragma unroll
            for (int i = 0; i < 4; i++) {
                float2 va = *(const float2*)&Ab[(i * 16 + g)     * 32 + ko];
                float2 vc = *(const float2*)&Ab[(i * 16 + g + 8) * 32 + ko];
                av[i][0] = __float_as_uint(va.x);
                av[i][1] = __float_as_uint(vc.x);
                av[i][2] = __float_as_uint(va.y);
                av[i][3] = __float_as_uint(vc.y);
            }
            unsigned bv[8][2];
#pragma unroll
            for (int j = 0; j < 8; j++) {
                float2 vb = *(const float2*)&Bb[(j * 8 + g) * 32 + ko];
                bv[j][0] = __float_as_uint(vb.x);
                bv[j][1] = __float_as_uint(vb.y);
            }
#pragma unroll
            for (int i = 0; i < 4; i++)
#pragma unroll
                for (int j = 0; j < 8; j++)
                    mma8(acc[i][j], av[i], bv[j]);
        }
    }

    const bool vpart = ROPE && (n0 >= 2 * C_);
#pragma unroll
    for (int i = 0; i < 4; i++) {
        const int rA = m0 + wm * 64 + i * 16 + g;
        const int rB = rA + 8;
        const size_t rowA = (size_t)rA * N;
        const size_t rowB = (size_t)rB * N;
        const int tA = rA & (T_ - 1);
        const int tB = rB & (T_ - 1);
        const int bA = rA >> 11;
#pragma unroll
        for (int j = 0; j < 8; j++) {
            const int col = n0 + wn * 64 + j * 8 + 2 * qd;
            float e0 = acc[i][j][0], o0 = acc[i][j][1];
            float e1 = acc[i][j][2], o1 = acc[i][j][3];
            if (ROPE) {
                if (!vpart) {
                    const int jj = (col & (D_ - 1)) >> 1;
                    float2 csA = tab[tA * 32 + jj];
                    float2 csB = tab[tB * 32 + jj];
                    float ne0 = e0 * csA.x - o0 * csA.y;
                    float no0 = e0 * csA.y + o0 * csA.x;
                    float ne1 = e1 * csB.x - o1 * csB.y;
                    float no1 = e1 * csB.y + o1 * csB.x;
                    *(float2*)&Y[rowA + col] =
                        make_float2(tf32r(ne0), tf32r(no0));
                    *(float2*)&Y[rowB + col] =
                        make_float2(tf32r(ne1), tf32r(no1));
                } else {
                    const int dv = col - 2 * C_;
                    float* vb = vT + ((size_t)bA * C_ + dv) * T_;
                    vb[tA]      = tf32r(e0);
                    vb[T_ + tA] = tf32r(o0);
                    vb[tB]      = tf32r(e1);
                    vb[T_ + tB] = tf32r(o1);
                }
            } else {
                *(float2*)&Y[rowA + col] = make_float2(e0, o0);
                *(float2*)&Y[rowB + col] = make_float2(e1, o1);
            }
        }
    }
}

// ---------------------------------------------------------------------------
// Flash attention (causal), FA-2 style, slot-remapped fragments.
// NO Q smem staging (direct LDG fragments) -> smem 73.7KB -> 3 CTAs/SM.
// log2e folded into Q scale -> softmax uses raw ex2.approx.
// P straight from S accumulators; V^T gives float2 PV B-fragments.
// ---------------------------------------------------------------------------
#define FST 72
#define VST 72

__global__ __launch_bounds__(128, 3) void flash_kernel(
    const float* __restrict__ qkv, const float* __restrict__ vT,
    float* __restrict__ o)
{
    extern __shared__ float sm[];
    float* Kb = sm;                     // 2 x 64*FST
    float* Vb = Kb + 128 * FST;         // 2 x 64*VST  (V^T tiles: [d][n])

    const int bh  = blockIdx.y;
    const int b   = bh >> 4;
    const int h   = bh & 15;
    const int q0  = (gridDim.x - 1 - blockIdx.x) * 64;
    const int tid = threadIdx.x;
    const int w   = tid >> 5;
    const int l   = tid & 31;
    const int g   = l >> 2;
    const int qd  = l & 3;
    const float scale = 0.125f * 1.44269504088896340736f;  // 1/sqrt(D)*log2(e)

    const size_t qbase = (size_t)(b * T_ + q0) * N3 + h * D_;
    const size_t vbase = ((size_t)b * C_ + h * D_) * T_;
    const size_t orow  = (size_t)(b * T_ + q0) * C_ + h * D_;

    auto kv_load = [&](int buf, int n0) {
        const size_t kbase = (size_t)(b * T_ + n0) * N3 + h * D_ + C_;
#pragma unroll
        for (int i = tid; i < 1024; i += 128) {
            int r = i >> 4, c = (i & 15) << 2;
            cp16(&Kb[buf * 64 * FST + r * FST + c],
                 &qkv[kbase + (size_t)r * N3 + c]);
            cp16(&Vb[buf * 64 * VST + r * VST + c],
                 &vT[vbase + (size_t)r * T_ + n0 + c]);
        }
    };

    kv_load(0, 0);
    CP_COMMIT();

    const int rA_loc = w * 16 + g;
    const int rB_loc = rA_loc + 8;

    // Q fragments: direct LDG (coalesced float2 per quad), scale + tf32r
    unsigned aq[8][4];
    {
        const float* qa = &qkv[qbase + (size_t)rA_loc * N3];
        const float* qb = &qkv[qbase + (size_t)rB_loc * N3];
#pragma unroll
        for (int kt = 0; kt < 8; kt++) {
            float2 va = *(const float2*)&qa[kt * 8 + 2 * qd];
            float2 vb = *(const float2*)&qb[kt * 8 + 2 * qd];
            aq[kt][0] = __float_as_uint(tf32r(va.x * scale));
            aq[kt][1] = __float_as_uint(tf32r(vb.x * scale));
            aq[kt][2] = __float_as_uint(tf32r(va.y * scale));
            aq[kt][3] = __float_as_uint(tf32r(vb.y * scale));
        }
    }

    float oacc[8][4];
#pragma unroll
    for (int nt = 0; nt < 8; nt++)
#pragma unroll
        for (int j = 0; j < 4; j++) oacc[nt][j] = 0.0f;
    float mA = -INFINITY, mB = -INFINITY, lA = 0.0f, lB = 0.0f;

    for (int n0 = 0; n0 <= q0; n0 += 64) {
        const int buf = (n0 >> 6) & 1;
        CP_WAIT(0);
        __syncthreads();
        if (n0 + 64 <= q0) {
            kv_load(buf ^ 1, n0 + 64);
            CP_COMMIT();
        }

        const float* Ks = &Kb[buf * 64 * FST];
        const float* Vs = &Vb[buf * 64 * VST];

        float s[8][4];
#pragma unroll
        for (int nt = 0; nt < 8; nt++)
#pragma unroll
            for (int j = 0; j < 4; j++) s[nt][j] = 0.0f;

#pragma unroll
        for (int kt = 0; kt < 8; kt++) {
            unsigned bb[8][2];
#pragma unroll
            for (int nt = 0; nt < 8; nt++) {
                float2 kb = *(const float2*)&Ks[(nt * 8 + g) * FST + kt * 8 + 2 * qd];
                bb[nt][0] = __float_as_uint(kb.x);
                bb[nt][1] = __float_as_uint(kb.y);
            }
#pragma unroll
            for (int nt = 0; nt < 8; nt++)
                mma8(s[nt], aq[kt], bb[nt]);
        }

        if (n0 == q0) {
#pragma unroll
            for (int nt = 0; nt < 8; nt++) {
                int c0 = nt * 8 + 2 * qd;
                if (c0     > rA_loc) s[nt][0] = -INFINITY;
                if (c0 + 1 > rA_loc) s[nt][1] = -INFINITY;
                if (c0     > rB_loc) s[nt][2] = -INFINITY;
                if (c0 + 1 > rB_loc) s[nt][3] = -INFINITY;
            }
        }

        float mxA = -INFINITY, mxB = -INFINITY;
#pragma unroll
        for (int nt = 0; nt < 8; nt++) {
            mxA = fmaxf(mxA, fmaxf(s[nt][0], s[nt][1]));
            mxB = fmaxf(mxB, fmaxf(s[nt][2], s[nt][3]));
        }
        mxA = fmaxf(mxA, __shfl_xor_sync(0xffffffffu, mxA, 1));
        mxA = fmaxf(mxA, __shfl_xor_sync(0xffffffffu, mxA, 2));
        mxB = fmaxf(mxB, __shfl_xor_sync(0xffffffffu, mxB, 1));
        mxB = fmaxf(mxB, __shfl_xor_sync(0xffffffffu, mxB, 2));

        float nmA = fmaxf(mA, mxA);
        float nmB = fmaxf(mB, mxB);
        float alA = ex2f(mA - nmA);
        float alB = ex2f(mB - nmB);
        mA = nmA; mB = nmB;

        float sumA = 0.0f, sumB = 0.0f;
#pragma unroll
        for (int nt = 0; nt < 8; nt++) {
            float p0 = ex2f(s[nt][0] - nmA);
            float p1 = ex2f(s[nt][1] - nmA);
            float p2 = ex2f(s[nt][2] - nmB);
            float p3 = ex2f(s[nt][3] - nmB);
            s[nt][0] = p0; s[nt][1] = p1; s[nt][2] = p2; s[nt][3] = p3;
            sumA += p0 + p1;
            sumB += p2 + p3;
        }
        sumA += __shfl_xor_sync(0xffffffffu, sumA, 1);
        sumA += __shfl_xor_sync(0xffffffffu, sumA, 2);
        sumB += __shfl_xor_sync(0xffffffffu, sumB, 1);
        sumB += __shfl_xor_sync(0xffffffffu, sumB, 2);
        lA = lA * alA + sumA;
        lB = lB * alB + sumB;

#pragma unroll
        for (int nt = 0; nt < 8; nt++) {
            oacc[nt][0] *= alA; oacc[nt][1] *= alA;
            oacc[nt][2] *= alB; oacc[nt][3] *= alB;
        }

        // O += P V : P straight from S accumulators; V^T float2 B-fragments
#pragma unroll
        for (int kt = 0; kt < 8; kt++) {
            unsigned ap[4];
            ap[0] = __float_as_uint(tf32r(s[kt][0]));
            ap[1] = __float_as_uint(tf32r(s[kt][2]));
            ap[2] = __float_as_uint(tf32r(s[kt][1]));
            ap[3] = __float_as_uint(tf32r(s[kt][3]));
            unsigned vv[8][2];
#pragma unroll
            for (int nt = 0; nt < 8; nt++) {
                float2 v2 = *(const float2*)&Vs[(nt * 8 + g) * VST + kt * 8 + 2 * qd];
                vv[nt][0] = __float_as_uint(v2.x);
                vv[nt][1] = __float_as_uint(v2.y);
            }
#pragma unroll
            for (int nt = 0; nt < 8; nt++)
                mma8(oacc[nt], ap, vv[nt]);
        }
    }

    const float rAi = 1.0f / lA;
    const float rBi = 1.0f / lB;
#pragma unroll
    for (int nt = 0; nt < 8; nt++) {
        int c0 = nt * 8 + 2 * qd;
        *(float2*)&o[orow + (size_t)rA_loc * C_ + c0] =
            make_float2(tf32r(oacc[nt][0] * rAi), tf32r(oacc[nt][1] * rAi));
        *(float2*)&o[orow + (size_t)rB_loc * C_ + c0] =
            make_float2(tf32r(oacc[nt][2] * rBi), tf32r(oacc[nt][3] * rBi));
    }
}

// ---------------------------------------------------------------------------
extern "C" void kernel_launch(void* const* d_in, const int* in_sizes, int n_in,
                              void* d_out, int out_size)
{
    (void)in_sizes; (void)n_in; (void)out_size;
    const float* x  = (const float*)d_in[0];
    const float* Wq = (const float*)d_in[1];
    const float* Wk = (const float*)d_in[2];
    const float* Wv = (const float*)d_in[3];
    const float* Wo = (const float*)d_in[4];
    float* out = (float*)d_out;

    float *qkv, *vT, *ob, *xc, *wc;
    float2* tab;
    cudaGetSymbolAddress((void**)&qkv, g_qkv);
    cudaGetSymbolAddress((void**)&vT,  g_vT);
    cudaGetSymbolAddress((void**)&ob,  g_o);
    cudaGetSymbolAddress((void**)&xc,  g_xc);
    cudaGetSymbolAddress((void**)&wc,  g_wc);
    cudaGetSymbolAddress((void**)&tab, g_rope_tab);

    float* wqkv = wc;
    float* woc  = wc + 3 * (size_t)C_ * C_;

    prep_kernel<<<(PREP_TOT + 255) / 256, 256>>>(x, Wq, Wk, Wv, Wo,
                                                 xc, wc, tab);

    const int gsmem = 6 * 4096 * (int)sizeof(float);        // 98,304 B
    cudaFuncSetAttribute(gemm_tn<true>,
                         cudaFuncAttributeMaxDynamicSharedMemorySize, gsmem);
    cudaFuncSetAttribute(gemm_tn<false>,
                         cudaFuncAttributeMaxDynamicSharedMemorySize, gsmem);

    gemm_tn<true><<<dim3(N3 / 128, M_ / 128), 128, gsmem>>>(
        xc, wqkv, qkv, vT, tab, M_, N3, C_);

    const int fsmem = (128 * FST + 128 * VST) * (int)sizeof(float);  // 73,728 B
    cudaFuncSetAttribute(flash_kernel,
                         cudaFuncAttributeMaxDynamicSharedMemorySize, fsmem);
    flash_kernel<<<dim3(T_ / 64, B_ * H_), 128, fsmem>>>(qkv, vT, ob);

    gemm_tn<false><<<dim3(C_ / 128, M_ / 128), 128, gsmem>>>(
        ob, woc, out, nullptr, tab, M_, C_, C_);
}